// round 1
// baseline (speedup 1.0000x reference)
#include <cuda_runtime.h>

#define HH 64
#define WW 64
#define HW 4096
#define CCH 256
#define NK 33

// Scratch: [4][256][4096] = Ef(b0), Ef(b1), Eg(b0), Eg(b1)
__device__ float g_E[4u * 256u * 4096u];

__constant__ int c_dx[NK] = {0, -1,-1,-1,0,0,1,1,1, -2,-2,-2,0,0,2,2,2,
                             -3,-3,-3,0,0,3,3,3, -4,-4,-4,0,0,4,4,4};
__constant__ int c_dy[NK] = {0, -1,0,1,-1,1,-1,0,1, -2,0,2,-2,2,-2,0,2,
                             -3,0,3,-3,3,-3,0,3, -4,0,4,-4,4,-4,0,4};

// ---------------------------------------------------------------------------
// Kernel 1: E = W (256x256) @ X (256x4096) + bias, per (which in {f,g}, batch)
// 128x128 block tile, kc=8, 256 threads, 8x8 microtile.
// ---------------------------------------------------------------------------
__global__ __launch_bounds__(256) void psla_gemm(
    const float* __restrict__ Ft, const float* __restrict__ Fte,
    const float* __restrict__ Wf, const float* __restrict__ bf,
    const float* __restrict__ Wg, const float* __restrict__ bg) {
  __shared__ float sA[8][132];  // [k][o] (transposed A tile)
  __shared__ float sB[8][132];  // [k][p]

  const int which = blockIdx.z >> 1;   // 0 = f, 1 = g
  const int b     = blockIdx.z & 1;
  const float* Wm   = which ? Wg : Wf;
  const float* bias = which ? bg : bf;
  const float* X    = (which ? Fte : Ft) + (size_t)b * CCH * HW;
  float* Eo = g_E + (size_t)blockIdx.z * CCH * HW;

  const int p0 = blockIdx.x * 128;
  const int o0 = blockIdx.y * 128;
  const int tid = threadIdx.x;
  const int tx = tid & 15, ty = tid >> 4;

  float acc[8][8];
#pragma unroll
  for (int i = 0; i < 8; i++)
#pragma unroll
    for (int j = 0; j < 8; j++) acc[i][j] = 0.f;

  const int arow = tid >> 1, acg = (tid & 1) * 4;
  const int brow = tid >> 5, bcol = (tid & 31) * 4;

  for (int k0 = 0; k0 < CCH; k0 += 8) {
    float4 av = *(const float4*)(Wm + (size_t)(o0 + arow) * CCH + k0 + acg);
    float4 bv = *(const float4*)(X + (size_t)(k0 + brow) * HW + p0 + bcol);
    __syncthreads();
    sA[acg + 0][arow] = av.x;
    sA[acg + 1][arow] = av.y;
    sA[acg + 2][arow] = av.z;
    sA[acg + 3][arow] = av.w;
    *(float4*)&sB[brow][bcol] = bv;
    __syncthreads();
#pragma unroll
    for (int kk = 0; kk < 8; kk++) {
      float a[8], bb[8];
      *(float4*)&a[0]  = *(const float4*)&sA[kk][ty * 8];
      *(float4*)&a[4]  = *(const float4*)&sA[kk][ty * 8 + 4];
      *(float4*)&bb[0] = *(const float4*)&sB[kk][tx * 8];
      *(float4*)&bb[4] = *(const float4*)&sB[kk][tx * 8 + 4];
#pragma unroll
      for (int i = 0; i < 8; i++)
#pragma unroll
        for (int j = 0; j < 8; j++) acc[i][j] = fmaf(a[i], bb[j], acc[i][j]);
    }
  }

#pragma unroll
  for (int i = 0; i < 8; i++) {
    const int o = o0 + ty * 8 + i;
    const float bvv = bias[o];
#pragma unroll
    for (int j = 0; j < 8; j += 4) {
      float4 v;
      v.x = acc[i][j + 0] + bvv;
      v.y = acc[i][j + 1] + bvv;
      v.z = acc[i][j + 2] + bvv;
      v.w = acc[i][j + 3] + bvv;
      *(float4*)(Eo + (size_t)o * HW + p0 + tx * 8 + j) = v;
    }
  }
}

// ---------------------------------------------------------------------------
// Kernel 2: sparse local attention.
// Block = 8x8 pixel tile, halo = 16x16 (pad 4). 256 threads = 64 px * 4 subs
// (each sub owns 8 channels of the current 32-channel chunk).
// smem layout [32 ch][257] -> bank = (c+q) mod 32, conflict-free for the
// warp shape (8 px adjacent q, 4 subs at c stride 8).
// ---------------------------------------------------------------------------
__global__ __launch_bounds__(256) void psla_attn(const float* __restrict__ Ft,
                                                 float* __restrict__ out) {
  __shared__ float sH[32][257];
  const int b = blockIdx.z;
  const int gx0 = blockIdx.x * 8, gy0 = blockIdx.y * 8;
  const int tid = threadIdx.x;
  const int px = tid >> 2, sub = tid & 3;
  const int lx = px & 7, ly = px >> 3;
  const int gx = gx0 + lx, gy = gy0 + ly;
  const int gp = gy * WW + gx;

  const float* Ef  = g_E + (size_t)b * CCH * HW;
  const float* Eg  = g_E + (size_t)(2 + b) * CCH * HW;
  const float* Ftb = Ft + (size_t)b * CCH * HW;

  // Per-thread halo-load coordinate (channel varies per iteration).
  const int hy = gy0 - 4 + (tid >> 4);
  const int hx = gx0 - 4 + (tid & 15);
  const bool hin = ((unsigned)hy < HH) && ((unsigned)hx < WW);
  const int haddr = hy * WW + hx;

  float aff[NK];
#pragma unroll
  for (int k = 0; k < NK; k++) aff[k] = 0.f;

  // ---- Phase A: aff[k] = <Eg(p), Ef(p + delta_k)> ----
  for (int c0 = 0; c0 < CCH; c0 += 32) {
    __syncthreads();
#pragma unroll 8
    for (int r = 0; r < 32; r++)
      sH[r][tid] = hin ? Ef[(size_t)(c0 + r) * HW + haddr] : 0.f;
    __syncthreads();

    float eg[8];
#pragma unroll
    for (int cc = 0; cc < 8; cc++)
      eg[cc] = Eg[(size_t)(c0 + sub * 8 + cc) * HW + gp];

#pragma unroll
    for (int k = 0; k < NK; k++) {
      const int dx = c_dx[k], dy = c_dy[k];
      if ((unsigned)(gy + dx) < HH && (unsigned)(gx + dy) < WW) {
        const int q = (ly + 4 + dx) * 16 + (lx + 4 + dy);
        float s = 0.f;
#pragma unroll
        for (int cc = 0; cc < 8; cc++)
          s = fmaf(eg[cc], sH[sub * 8 + cc][q], s);
        aff[k] += s;
      }
    }
  }

  // Reduce partial dot products across the 4 channel-subgroups (same quad).
#pragma unroll
  for (int k = 0; k < NK; k++) {
    aff[k] += __shfl_xor_sync(0xffffffffu, aff[k], 1);
    aff[k] += __shfl_xor_sync(0xffffffffu, aff[k], 2);
  }

  // ---- Softmax over valid offsets (k=0 always valid) ----
  float m = aff[0];
#pragma unroll
  for (int k = 1; k < NK; k++)
    if ((unsigned)(gy + c_dx[k]) < HH && (unsigned)(gx + c_dy[k]) < WW)
      m = fmaxf(m, aff[k]);
  float ssum = 0.f;
#pragma unroll
  for (int k = 0; k < NK; k++) {
    if ((unsigned)(gy + c_dx[k]) < HH && (unsigned)(gx + c_dy[k]) < WW) {
      aff[k] = __expf(aff[k] - m);
      ssum += aff[k];
    } else {
      aff[k] = 0.f;
    }
  }
  const float inv = 1.f / ssum;
#pragma unroll
  for (int k = 0; k < NK; k++) aff[k] *= inv;

  // ---- Phase B: out(c,p) = sum_k w_k * Ft(c, p + delta_k) ----
  for (int c0 = 0; c0 < CCH; c0 += 32) {
    __syncthreads();
#pragma unroll 8
    for (int r = 0; r < 32; r++)
      sH[r][tid] = hin ? Ftb[(size_t)(c0 + r) * HW + haddr] : 0.f;
    __syncthreads();

    float acc[8];
#pragma unroll
    for (int cc = 0; cc < 8; cc++) acc[cc] = 0.f;

#pragma unroll
    for (int k = 0; k < NK; k++) {
      const int dx = c_dx[k], dy = c_dy[k];
      if ((unsigned)(gy + dx) < HH && (unsigned)(gx + dy) < WW) {
        const int q = (ly + 4 + dx) * 16 + (lx + 4 + dy);
        const float wk = aff[k];
#pragma unroll
        for (int cc = 0; cc < 8; cc++)
          acc[cc] = fmaf(wk, sH[sub * 8 + cc][q], acc[cc]);
      }
    }

#pragma unroll
    for (int cc = 0; cc < 8; cc++)
      out[(size_t)(b * CCH + c0 + sub * 8 + cc) * HW + gp] = acc[cc];
  }
}

// ---------------------------------------------------------------------------
extern "C" void kernel_launch(void* const* d_in, const int* in_sizes, int n_in,
                              void* d_out, int out_size) {
  const float* Ft  = (const float*)d_in[0];
  const float* Fte = (const float*)d_in[1];
  const float* Wf  = (const float*)d_in[2];
  const float* bf  = (const float*)d_in[3];
  const float* Wg  = (const float*)d_in[4];
  const float* bg  = (const float*)d_in[5];
  float* out = (float*)d_out;

  dim3 gg(32, 2, 4);  // p-tiles, o-tiles, (which*2 + batch)
  psla_gemm<<<gg, 256>>>(Ft, Fte, Wf, bf, Wg, bg);

  dim3 ga(8, 8, 2);   // W/8, H/8, B
  psla_attn<<<ga, 256>>>(Ft, out);
}

// round 2
// speedup vs baseline: 1.0461x; 1.0461x over previous
#include <cuda_runtime.h>

#define HH 64
#define WW 64
#define HW 4096
#define CCH 256
#define NK 33

// Scratch: [4][256][4096] = Ef(b0), Ef(b1), Eg(b0), Eg(b1)
__device__ float g_E[4u * 256u * 4096u];

__constant__ int c_dx[NK] = {0, -1,-1,-1,0,0,1,1,1, -2,-2,-2,0,0,2,2,2,
                             -3,-3,-3,0,0,3,3,3, -4,-4,-4,0,0,4,4,4};
__constant__ int c_dy[NK] = {0, -1,0,1,-1,1,-1,0,1, -2,0,2,-2,2,-2,0,2,
                             -3,0,3,-3,3,-3,0,3, -4,0,4,-4,4,-4,0,4};

// ---------------------------------------------------------------------------
// Kernel 1: E = W (256x256) @ X (256x4096) + bias, per (which in {f,g}, batch)
// 128x128 block tile, kc=8, 256 threads, 8x8 microtile. (FMA-bound, ~81% of
// fp32 peak already — unchanged this round.)
// ---------------------------------------------------------------------------
__global__ __launch_bounds__(256) void psla_gemm(
    const float* __restrict__ Ft, const float* __restrict__ Fte,
    const float* __restrict__ Wf, const float* __restrict__ bf,
    const float* __restrict__ Wg, const float* __restrict__ bg) {
  __shared__ float sA[8][132];  // [k][o] (transposed A tile)
  __shared__ float sB[8][132];  // [k][p]

  const int which = blockIdx.z >> 1;   // 0 = f, 1 = g
  const int b     = blockIdx.z & 1;
  const float* Wm   = which ? Wg : Wf;
  const float* bias = which ? bg : bf;
  const float* X    = (which ? Fte : Ft) + (size_t)b * CCH * HW;
  float* Eo = g_E + (size_t)blockIdx.z * CCH * HW;

  const int p0 = blockIdx.x * 128;
  const int o0 = blockIdx.y * 128;
  const int tid = threadIdx.x;
  const int tx = tid & 15, ty = tid >> 4;

  float acc[8][8];
#pragma unroll
  for (int i = 0; i < 8; i++)
#pragma unroll
    for (int j = 0; j < 8; j++) acc[i][j] = 0.f;

  const int arow = tid >> 1, acg = (tid & 1) * 4;
  const int brow = tid >> 5, bcol = (tid & 31) * 4;

  for (int k0 = 0; k0 < CCH; k0 += 8) {
    float4 av = *(const float4*)(Wm + (size_t)(o0 + arow) * CCH + k0 + acg);
    float4 bv = *(const float4*)(X + (size_t)(k0 + brow) * HW + p0 + bcol);
    __syncthreads();
    sA[acg + 0][arow] = av.x;
    sA[acg + 1][arow] = av.y;
    sA[acg + 2][arow] = av.z;
    sA[acg + 3][arow] = av.w;
    *(float4*)&sB[brow][bcol] = bv;
    __syncthreads();
#pragma unroll
    for (int kk = 0; kk < 8; kk++) {
      float a[8], bb[8];
      *(float4*)&a[0]  = *(const float4*)&sA[kk][ty * 8];
      *(float4*)&a[4]  = *(const float4*)&sA[kk][ty * 8 + 4];
      *(float4*)&bb[0] = *(const float4*)&sB[kk][tx * 8];
      *(float4*)&bb[4] = *(const float4*)&sB[kk][tx * 8 + 4];
#pragma unroll
      for (int i = 0; i < 8; i++)
#pragma unroll
        for (int j = 0; j < 8; j++) acc[i][j] = fmaf(a[i], bb[j], acc[i][j]);
    }
  }

#pragma unroll
  for (int i = 0; i < 8; i++) {
    const int o = o0 + ty * 8 + i;
    const float bvv = bias[o];
#pragma unroll
    for (int j = 0; j < 8; j += 4) {
      float4 v;
      v.x = acc[i][j + 0] + bvv;
      v.y = acc[i][j + 1] + bvv;
      v.z = acc[i][j + 2] + bvv;
      v.w = acc[i][j + 3] + bvv;
      *(float4*)(Eo + (size_t)o * HW + p0 + tx * 8 + j) = v;
    }
  }
}

// ---------------------------------------------------------------------------
// Kernel 2: sparse local attention, v2.
// 512 threads = 64 px * 8 channel-subgroups of 4.
// Double-buffered halo in dynamic smem (2 x 32ch x 257), software-pipelined:
// next chunk's LDGs are issued before current chunk's compute, one sync/chunk.
// ---------------------------------------------------------------------------
__global__ __launch_bounds__(512) void psla_attn(const float* __restrict__ Ft,
                                                 float* __restrict__ out) {
  extern __shared__ float sm[];
  float (*sH)[32][257] = (float (*)[32][257])sm;

  const int b = blockIdx.z;
  const int gx0 = blockIdx.x * 8, gy0 = blockIdx.y * 8;
  const int tid = threadIdx.x;
  const int px = tid >> 3, sub = tid & 7;
  const int lx = px & 7, ly = px >> 3;
  const int gx = gx0 + lx, gy = gy0 + ly;
  const int gp = gy * WW + gx;

  const float* Ef  = g_E + (size_t)b * CCH * HW;
  const float* Eg  = g_E + (size_t)(2 + b) * CCH * HW;
  const float* Ftb = Ft + (size_t)b * CCH * HW;

  // Halo-load mapping: q = site index (fixed per thread), rows r0+2i vary.
  const int q  = tid & 255;
  const int r0 = tid >> 8;                 // 0 or 1
  const int hy = gy0 - 4 + (q >> 4);
  const int hx = gx0 - 4 + (q & 15);
  const bool hin = ((unsigned)hy < HH) && ((unsigned)hx < WW);
  const int haddr = hy * WW + hx;

  // Validity bitmask over the 33 offsets for this pixel.
  unsigned long long vmask = 0ull;
#pragma unroll
  for (int k = 0; k < NK; k++)
    if ((unsigned)(gy + c_dx[k]) < HH && (unsigned)(gx + c_dy[k]) < WW)
      vmask |= (1ull << k);

  const int chbase = sub * 4;

  float aff[NK];
#pragma unroll
  for (int k = 0; k < NK; k++) aff[k] = 0.f;

  float h[16], hn[16], eg[4], egn[4];

  // ==== Phase A: aff[k] = <Eg(p), Ef(p + delta_k)> ====
#pragma unroll
  for (int i = 0; i < 16; i++)
    h[i] = hin ? Ef[(size_t)(r0 + 2 * i) * HW + haddr] : 0.f;
#pragma unroll
  for (int cc = 0; cc < 4; cc++)
    eg[cc] = Eg[(size_t)(chbase + cc) * HW + gp];
#pragma unroll
  for (int i = 0; i < 16; i++) sH[0][r0 + 2 * i][q] = h[i];
  __syncthreads();

  for (int c0 = 0; c0 < 8; c0++) {
    if (c0 < 7) {
      const int base = (c0 + 1) * 32;
#pragma unroll
      for (int i = 0; i < 16; i++)
        hn[i] = hin ? Ef[(size_t)(base + r0 + 2 * i) * HW + haddr] : 0.f;
#pragma unroll
      for (int cc = 0; cc < 4; cc++)
        egn[cc] = Eg[(size_t)(base + chbase + cc) * HW + gp];
    }
    const int buf = c0 & 1;
#pragma unroll
    for (int k = 0; k < NK; k++) {
      if ((vmask >> k) & 1ull) {
        const int qq = (ly + 4 + c_dx[k]) * 16 + (lx + 4 + c_dy[k]);
        float s = 0.f;
#pragma unroll
        for (int cc = 0; cc < 4; cc++)
          s = fmaf(eg[cc], sH[buf][chbase + cc][qq], s);
        aff[k] += s;
      }
    }
    if (c0 < 7) {
#pragma unroll
      for (int i = 0; i < 16; i++) sH[buf ^ 1][r0 + 2 * i][q] = hn[i];
#pragma unroll
      for (int cc = 0; cc < 4; cc++) eg[cc] = egn[cc];
    }
    __syncthreads();
  }

  // Reduce partial dots across the 8 channel-subgroups (lanes xor 1,2,4).
#pragma unroll
  for (int k = 0; k < NK; k++) {
    aff[k] += __shfl_xor_sync(0xffffffffu, aff[k], 1);
    aff[k] += __shfl_xor_sync(0xffffffffu, aff[k], 2);
    aff[k] += __shfl_xor_sync(0xffffffffu, aff[k], 4);
  }

  // ==== Softmax over valid offsets (k=0 always valid) ====
  float m = aff[0];
#pragma unroll
  for (int k = 1; k < NK; k++)
    if ((vmask >> k) & 1ull) m = fmaxf(m, aff[k]);
  float ssum = 0.f;
#pragma unroll
  for (int k = 0; k < NK; k++) {
    if ((vmask >> k) & 1ull) {
      aff[k] = __expf(aff[k] - m);
      ssum += aff[k];
    } else {
      aff[k] = 0.f;
    }
  }
  const float inv = 1.f / ssum;
#pragma unroll
  for (int k = 0; k < NK; k++) aff[k] *= inv;

  // ==== Phase B: out(c,p) = sum_k w_k * Ft(c, p + delta_k) ====
#pragma unroll
  for (int i = 0; i < 16; i++)
    h[i] = hin ? Ftb[(size_t)(r0 + 2 * i) * HW + haddr] : 0.f;
#pragma unroll
  for (int i = 0; i < 16; i++) sH[0][r0 + 2 * i][q] = h[i];
  __syncthreads();

  for (int c0 = 0; c0 < 8; c0++) {
    if (c0 < 7) {
      const int base = (c0 + 1) * 32;
#pragma unroll
      for (int i = 0; i < 16; i++)
        hn[i] = hin ? Ftb[(size_t)(base + r0 + 2 * i) * HW + haddr] : 0.f;
    }
    const int buf = c0 & 1;

    float acc[4];
#pragma unroll
    for (int cc = 0; cc < 4; cc++) acc[cc] = 0.f;

#pragma unroll
    for (int k = 0; k < NK; k++) {
      if ((vmask >> k) & 1ull) {
        const int qq = (ly + 4 + c_dx[k]) * 16 + (lx + 4 + c_dy[k]);
        const float wk = aff[k];
#pragma unroll
        for (int cc = 0; cc < 4; cc++)
          acc[cc] = fmaf(wk, sH[buf][chbase + cc][qq], acc[cc]);
      }
    }

#pragma unroll
    for (int cc = 0; cc < 4; cc++)
      out[(size_t)(b * CCH + c0 * 32 + chbase + cc) * HW + gp] = acc[cc];

    if (c0 < 7) {
#pragma unroll
      for (int i = 0; i < 16; i++) sH[buf ^ 1][r0 + 2 * i][q] = hn[i];
    }
    __syncthreads();
  }
}

// ---------------------------------------------------------------------------
extern "C" void kernel_launch(void* const* d_in, const int* in_sizes, int n_in,
                              void* d_out, int out_size) {
  const float* Ft  = (const float*)d_in[0];
  const float* Fte = (const float*)d_in[1];
  const float* Wf  = (const float*)d_in[2];
  const float* bf  = (const float*)d_in[3];
  const float* Wg  = (const float*)d_in[4];
  const float* bg  = (const float*)d_in[5];
  float* out = (float*)d_out;

  const int attn_smem = 2 * 32 * 257 * (int)sizeof(float);  // 65792 B
  cudaFuncSetAttribute(psla_attn, cudaFuncAttributeMaxDynamicSharedMemorySize,
                       attn_smem);

  dim3 gg(32, 2, 4);  // p-tiles, o-tiles, (which*2 + batch)
  psla_gemm<<<gg, 256>>>(Ft, Fte, Wf, bf, Wg, bg);

  dim3 ga(8, 8, 2);   // W/8, H/8, B
  psla_attn<<<ga, 512, attn_smem>>>(Ft, out);
}

// round 3
// speedup vs baseline: 1.3104x; 1.2527x over previous
#include <cuda_runtime.h>

#define HH 64
#define WW 64
#define HW 4096
#define CCH 256
#define NK 33

// Scratch: [4][256][4096] = Ef(b0), Ef(b1), Eg(b0), Eg(b1)
__device__ float g_E[4u * 256u * 4096u];

// ---------------------------------------------------------------------------
// f32x2 packed helpers (sm_103a FFMA2 — only reachable via PTX fma.rn.f32x2)
// ---------------------------------------------------------------------------
__device__ __forceinline__ unsigned long long pack2_bcast(float x) {
  unsigned long long r;
  asm("mov.b64 %0, {%1, %1};" : "=l"(r) : "f"(x));
  return r;
}
__device__ __forceinline__ unsigned long long ffma2(unsigned long long a,
                                                    unsigned long long b,
                                                    unsigned long long c) {
  unsigned long long d;
  asm("fma.rn.f32x2 %0, %1, %2, %3;" : "=l"(d) : "l"(a), "l"(b), "l"(c));
  return d;
}
__device__ __forceinline__ void unpack2(unsigned long long v, float& lo, float& hi) {
  asm("mov.b64 {%0, %1}, %2;" : "=f"(lo), "=f"(hi) : "l"(v));
}

// ---------------------------------------------------------------------------
// Kernel 1: E = W (256x256) @ X (256x4096) + bias, per (which in {f,g}, batch)
// 128x128 block tile, kc=8, 256 threads, 8x8 microtile, FFMA2 core.
// ---------------------------------------------------------------------------
__global__ __launch_bounds__(256, 2) void psla_gemm(
    const float* __restrict__ Ft, const float* __restrict__ Fte,
    const float* __restrict__ Wf, const float* __restrict__ bf,
    const float* __restrict__ Wg, const float* __restrict__ bg) {
  __shared__ float sA[8][132];  // [k][o] (transposed A tile)
  __shared__ float sB[8][132];  // [k][p]

  const int which = blockIdx.z >> 1;   // 0 = f, 1 = g
  const int b     = blockIdx.z & 1;
  const float* Wm   = which ? Wg : Wf;
  const float* bias = which ? bg : bf;
  const float* X    = (which ? Fte : Ft) + (size_t)b * CCH * HW;
  float* Eo = g_E + (size_t)blockIdx.z * CCH * HW;

  const int p0 = blockIdx.x * 128;
  const int o0 = blockIdx.y * 128;
  const int tid = threadIdx.x;
  const int tx = tid & 15, ty = tid >> 4;

  unsigned long long acc2[8][4];
#pragma unroll
  for (int i = 0; i < 8; i++)
#pragma unroll
    for (int j = 0; j < 4; j++) acc2[i][j] = 0ull;

  const int arow = tid >> 1, acg = (tid & 1) * 4;
  const int brow = tid >> 5, bcol = (tid & 31) * 4;

  for (int k0 = 0; k0 < CCH; k0 += 8) {
    float4 av = *(const float4*)(Wm + (size_t)(o0 + arow) * CCH + k0 + acg);
    float4 bv = *(const float4*)(X + (size_t)(k0 + brow) * HW + p0 + bcol);
    __syncthreads();
    sA[acg + 0][arow] = av.x;
    sA[acg + 1][arow] = av.y;
    sA[acg + 2][arow] = av.z;
    sA[acg + 3][arow] = av.w;
    *(float4*)&sB[brow][bcol] = bv;
    __syncthreads();
#pragma unroll
    for (int kk = 0; kk < 8; kk++) {
      float a[8];
      *(float4*)&a[0] = *(const float4*)&sA[kk][ty * 8];
      *(float4*)&a[4] = *(const float4*)&sA[kk][ty * 8 + 4];
      // b pairs read straight from smem as 64-bit lanes (no pack MOVs)
      unsigned long long b2[4];
      ulonglong2 bl0 = *(const ulonglong2*)&sB[kk][tx * 8];
      ulonglong2 bl1 = *(const ulonglong2*)&sB[kk][tx * 8 + 4];
      b2[0] = bl0.x; b2[1] = bl0.y; b2[2] = bl1.x; b2[3] = bl1.y;
      unsigned long long a2[8];
#pragma unroll
      for (int i = 0; i < 8; i++) a2[i] = pack2_bcast(a[i]);
#pragma unroll
      for (int i = 0; i < 8; i++)
#pragma unroll
        for (int j = 0; j < 4; j++) acc2[i][j] = ffma2(a2[i], b2[j], acc2[i][j]);
    }
  }

#pragma unroll
  for (int i = 0; i < 8; i++) {
    const int o = o0 + ty * 8 + i;
    const float bvv = bias[o];
    float r[8];
#pragma unroll
    for (int j = 0; j < 4; j++) unpack2(acc2[i][j], r[2 * j], r[2 * j + 1]);
#pragma unroll
    for (int j = 0; j < 8; j += 4) {
      float4 v;
      v.x = r[j + 0] + bvv;
      v.y = r[j + 1] + bvv;
      v.z = r[j + 2] + bvv;
      v.w = r[j + 3] + bvv;
      *(float4*)(Eo + (size_t)o * HW + p0 + tx * 8 + j) = v;
    }
  }
}

// ---------------------------------------------------------------------------
// Kernel 2: sparse local attention, v3.
// 512 threads = 64 px * 8 channel-subgroups of 4.
// smem layout: [2 buffers][256 halo sites][36 floats] (32 ch + pad 4).
// Inner loop per k: 1 LDS.128 with compile-time immediate offset + 4 FFMA.
// No per-k predication: out-of-image halo is zero-filled, so invalid k
// contribute exactly 0; validity is applied only in the softmax mask.
// ---------------------------------------------------------------------------
#define SST 36
#define BUFF (256 * SST)

__device__ __forceinline__ void halo_fetch(const float* __restrict__ P,
                                           int base, int cg0, bool hin,
                                           int haddr, float4* hv) {
#pragma unroll
  for (int j = 0; j < 4; j++) {
    const int c = base + (cg0 + 2 * j) * 4;
    float4 v;
    v.x = hin ? P[(size_t)(c + 0) * HW + haddr] : 0.f;
    v.y = hin ? P[(size_t)(c + 1) * HW + haddr] : 0.f;
    v.z = hin ? P[(size_t)(c + 2) * HW + haddr] : 0.f;
    v.w = hin ? P[(size_t)(c + 3) * HW + haddr] : 0.f;
    hv[j] = v;
  }
}
__device__ __forceinline__ void halo_store(float* bufq, int cg0,
                                           const float4* hv) {
#pragma unroll
  for (int j = 0; j < 4; j++)
    *(float4*)(bufq + (cg0 + 2 * j) * 4) = hv[j];
}

__global__ __launch_bounds__(512) void psla_attn(const float* __restrict__ Ft,
                                                 float* __restrict__ out) {
  extern __shared__ float sm[];
  constexpr int kdx[NK] = {0, -1,-1,-1,0,0,1,1,1, -2,-2,-2,0,0,2,2,2,
                           -3,-3,-3,0,0,3,3,3, -4,-4,-4,0,0,4,4,4};
  constexpr int kdy[NK] = {0, -1,0,1,-1,1,-1,0,1, -2,0,2,-2,2,-2,0,2,
                           -3,0,3,-3,3,-3,0,3, -4,0,4,-4,4,-4,0,4};

  const int b = blockIdx.z;
  const int gx0 = blockIdx.x * 8, gy0 = blockIdx.y * 8;
  const int tid = threadIdx.x;
  const int px = tid >> 3, sub = tid & 7;
  const int lx = px & 7, ly = px >> 3;
  const int gx = gx0 + lx, gy = gy0 + ly;
  const int gp = gy * WW + gx;

  const float* Ef  = g_E + (size_t)b * CCH * HW;
  const float* Eg  = g_E + (size_t)(2 + b) * CCH * HW;
  const float* Ftb = Ft + (size_t)b * CCH * HW;

  // Halo-load mapping: each thread owns site q, channel groups cg0+2j.
  const int q   = tid & 255;
  const int cg0 = tid >> 8;  // 0 or 1
  const int hy = gy0 - 4 + (q >> 4);
  const int hx = gx0 - 4 + (q & 15);
  const bool hin = ((unsigned)hy < HH) && ((unsigned)hx < WW);
  const int haddr = hy * WW + hx;
  float* const myq0 = sm + q * SST;  // this thread's store row, buffer 0

  // Compute-side base: center site row + this thread's 4-channel group.
  const float* const cbase = sm + ((ly + 4) * 16 + (lx + 4)) * SST + sub * 4;

  // Validity bitmask over the 33 offsets for this pixel.
  unsigned long long vmask = 0ull;
#pragma unroll
  for (int k = 0; k < NK; k++)
    if ((unsigned)(gy + kdx[k]) < HH && (unsigned)(gx + kdy[k]) < WW)
      vmask |= (1ull << k);

  float aff[NK];
#pragma unroll
  for (int k = 0; k < NK; k++) aff[k] = 0.f;

  float4 hv[4], hn[4];
  float eg[4], egn[4];

  // ==== Phase A: aff[k] = <Eg(p), Ef(p + delta_k)> ====
  halo_fetch(Ef, 0, cg0, hin, haddr, hv);
#pragma unroll
  for (int cc = 0; cc < 4; cc++) eg[cc] = Eg[(size_t)(sub * 4 + cc) * HW + gp];
  halo_store(myq0, cg0, hv);
  __syncthreads();

  for (int c0 = 0; c0 < 8; c0++) {
    if (c0 < 7) {
      const int base = (c0 + 1) * 32;
      halo_fetch(Ef, base, cg0, hin, haddr, hn);
#pragma unroll
      for (int cc = 0; cc < 4; cc++)
        egn[cc] = Eg[(size_t)(base + sub * 4 + cc) * HW + gp];
    }
    const float* bp = cbase + (c0 & 1) * BUFF;
#pragma unroll
    for (int k = 0; k < NK; k++) {
      const float4 v = *(const float4*)(bp + (kdx[k] * 16 + kdy[k]) * SST);
      float s = fmaf(eg[0], v.x, 0.f);
      s = fmaf(eg[1], v.y, s);
      s = fmaf(eg[2], v.z, s);
      s = fmaf(eg[3], v.w, s);
      aff[k] += s;
    }
    if (c0 < 7) {
      halo_store(myq0 + ((c0 & 1) ^ 1) * BUFF, cg0, hn);
#pragma unroll
      for (int cc = 0; cc < 4; cc++) eg[cc] = egn[cc];
    }
    __syncthreads();
  }

  // Reduce partial dots across the 8 channel-subgroups (lanes xor 1,2,4).
#pragma unroll
  for (int k = 0; k < NK; k++) {
    aff[k] += __shfl_xor_sync(0xffffffffu, aff[k], 1);
    aff[k] += __shfl_xor_sync(0xffffffffu, aff[k], 2);
    aff[k] += __shfl_xor_sync(0xffffffffu, aff[k], 4);
  }

  // ==== Softmax over valid offsets (k=0 always valid) ====
  float m = aff[0];
#pragma unroll
  for (int k = 1; k < NK; k++)
    if ((vmask >> k) & 1ull) m = fmaxf(m, aff[k]);
  float ssum = 0.f;
#pragma unroll
  for (int k = 0; k < NK; k++) {
    if ((vmask >> k) & 1ull) {
      aff[k] = __expf(aff[k] - m);
      ssum += aff[k];
    } else {
      aff[k] = 0.f;
    }
  }
  const float inv = 1.f / ssum;
#pragma unroll
  for (int k = 0; k < NK; k++) aff[k] *= inv;

  // ==== Phase B: out(c,p) = sum_k w_k * Ft(c, p + delta_k) ====
  halo_fetch(Ftb, 0, cg0, hin, haddr, hv);
  halo_store(myq0, cg0, hv);
  __syncthreads();

  for (int c0 = 0; c0 < 8; c0++) {
    if (c0 < 7) halo_fetch(Ftb, (c0 + 1) * 32, cg0, hin, haddr, hn);

    const float* bp = cbase + (c0 & 1) * BUFF;
    float acc[4] = {0.f, 0.f, 0.f, 0.f};
#pragma unroll
    for (int k = 0; k < NK; k++) {
      const float4 v = *(const float4*)(bp + (kdx[k] * 16 + kdy[k]) * SST);
      const float wk = aff[k];
      acc[0] = fmaf(wk, v.x, acc[0]);
      acc[1] = fmaf(wk, v.y, acc[1]);
      acc[2] = fmaf(wk, v.z, acc[2]);
      acc[3] = fmaf(wk, v.w, acc[3]);
    }
#pragma unroll
    for (int cc = 0; cc < 4; cc++)
      out[(size_t)(b * CCH + c0 * 32 + sub * 4 + cc) * HW + gp] = acc[cc];

    if (c0 < 7) halo_store(myq0 + ((c0 & 1) ^ 1) * BUFF, cg0, hn);
    __syncthreads();
  }
}

// ---------------------------------------------------------------------------
extern "C" void kernel_launch(void* const* d_in, const int* in_sizes, int n_in,
                              void* d_out, int out_size) {
  const float* Ft  = (const float*)d_in[0];
  const float* Fte = (const float*)d_in[1];
  const float* Wf  = (const float*)d_in[2];
  const float* bf  = (const float*)d_in[3];
  const float* Wg  = (const float*)d_in[4];
  const float* bg  = (const float*)d_in[5];
  float* out = (float*)d_out;

  const int attn_smem = 2 * BUFF * (int)sizeof(float);  // 73728 B
  cudaFuncSetAttribute(psla_attn, cudaFuncAttributeMaxDynamicSharedMemorySize,
                       attn_smem);

  dim3 gg(32, 2, 4);  // p-tiles, o-tiles, (which*2 + batch)
  psla_gemm<<<gg, 256>>>(Ft, Fte, Wf, bf, Wg, bg);

  dim3 ga(8, 8, 2);   // W/8, H/8, B
  psla_attn<<<ga, 512, attn_smem>>>(Ft, out);
}